// round 1
// baseline (speedup 1.0000x reference)
#include <cuda_runtime.h>
#include <cstdint>

// Problem constants
#define C_CH   1024
#define H_     100
#define W_     50
#define POOLSZ 7
#define NROI   256
#define NCLS   21
#define KDIM   (C_CH * POOLSZ * POOLSZ)   // 50176
#define FCOUT  1024
#define NSPLIT 49                          // 50176 / 1024
#define KCHUNK 1024                        // K per split

// Scratch (no cudaMalloc allowed; __device__ globals are the sanctioned path)
__device__ float g_pooled[NROI * KDIM];              // ~51.4 MB
__device__ float g_part[NSPLIT * NROI * FCOUT];      // ~51.4 MB
__device__ float g_r[NROI * FCOUT];                  // 1 MB

// ---------------------------------------------------------------------------
// Kernel 1: ROI adaptive max-pool 7x7.
// One thread per (roi, c, i, j) output element.
// Reference semantics: rois = max(proposals,0)//16, with proposal row
// [x1,y1,x2,y2] mapped as h0=x1c, w0=y1c, h1=x2c, w1=y2c (x is the H axis).
// Bins: start = floor(i*s/7), end = ceil((i+1)*s/7)  (never empty for s>=1).
// ---------------------------------------------------------------------------
__global__ void pool_kernel(const float* __restrict__ fmap,
                            const int*   __restrict__ props)
{
    int roi = blockIdx.y;
    int idx = blockIdx.x * blockDim.x + threadIdx.x;   // 0..50175
    if (idx >= KDIM) return;

    int x1 = props[roi * 4 + 0];
    int y1 = props[roi * 4 + 1];
    int x2 = props[roi * 4 + 2];
    int y2 = props[roi * 4 + 3];
    int h0 = max(x1, 0) >> 4;
    int w0 = max(y1, 0) >> 4;
    int h1 = max(x2, 0) >> 4;
    int w1 = max(y2, 0) >> 4;
    int sh = h1 - h0 + 1;
    int sw = w1 - w0 + 1;

    int c = idx / 49;
    int p = idx - c * 49;
    int i = p / 7;
    int j = p - i * 7;

    int hs = h0 + (i * sh) / 7;
    int he = h0 + ((i + 1) * sh + 6) / 7;   // ceil
    int ws = w0 + (j * sw) / 7;
    int we = w0 + ((j + 1) * sw + 6) / 7;   // ceil

    const float* base = fmap + (size_t)c * (H_ * W_);
    float m = -3.402823466e38f;
    for (int hh = hs; hh < he; ++hh) {
        const float* rowp = base + hh * W_;
        for (int ww = ws; ww < we; ++ww)
            m = fmaxf(m, __ldg(rowp + ww));
    }
    g_pooled[(size_t)roi * KDIM + idx] = m;
}

// ---------------------------------------------------------------------------
// Kernel 2: split-K fp32 GEMM.
// C[m][n] = sum_k A[m][k] * B[n][k]
//   A = g_pooled [256 x 50176]  (row-major, K contiguous)
//   B = fc_w     [1024 x 50176] (row-major, K contiguous)
// Each block: 128x128 output tile, one K chunk of 1024 -> writes partial
// sums to g_part[z][m][n] (deterministic: no atomics).
// 256 threads, 8x8 micro-tile per thread (split 2x2 quads of 4).
// ---------------------------------------------------------------------------
#define BM 128
#define BN 128
#define BK 8

__global__ void __launch_bounds__(256, 2)
gemm_kernel(const float* __restrict__ B /* fc_w */)
{
    __shared__ float As[BK][BM];
    __shared__ float Bs[BK][BN];

    const int n0 = blockIdx.x * BN;
    const int m0 = blockIdx.y * BM;
    const int z  = blockIdx.z;
    const int k0base = z * KCHUNK;

    const int tid = threadIdx.x;
    const int tx  = tid & 15;    // 0..15  -> N
    const int ty  = tid >> 4;    // 0..15  -> M

    // Global->shared load mapping: threads 0..127 load k-planes 0..3,
    // threads 128..255 load k-planes 4..7; lrow = tid % 128.
    // -> STS conflict-free, 16B loads land on full 32B sectors.
    const int lrow = tid & 127;
    const int lk4  = (tid >> 7) * 4;

    const float* Arow = g_pooled + (size_t)(m0 + lrow) * KDIM + k0base + lk4;
    const float* Brow = B        + (size_t)(n0 + lrow) * KDIM + k0base + lk4;

    float acc[8][8];
#pragma unroll
    for (int i = 0; i < 8; ++i)
#pragma unroll
        for (int j = 0; j < 8; ++j) acc[i][j] = 0.f;

    for (int kt = 0; kt < KCHUNK; kt += BK) {
        float4 a4 = *(const float4*)(Arow + kt);
        float4 b4 = *(const float4*)(Brow + kt);
        As[lk4 + 0][lrow] = a4.x;
        As[lk4 + 1][lrow] = a4.y;
        As[lk4 + 2][lrow] = a4.z;
        As[lk4 + 3][lrow] = a4.w;
        Bs[lk4 + 0][lrow] = b4.x;
        Bs[lk4 + 1][lrow] = b4.y;
        Bs[lk4 + 2][lrow] = b4.z;
        Bs[lk4 + 3][lrow] = b4.w;
        __syncthreads();

#pragma unroll
        for (int kk = 0; kk < BK; ++kk) {
            // vectorized, broadcast/contig LDS (two float4 per operand)
            float4 am0 = *(const float4*)&As[kk][ty * 4];
            float4 am1 = *(const float4*)&As[kk][64 + ty * 4];
            float4 bn0 = *(const float4*)&Bs[kk][tx * 4];
            float4 bn1 = *(const float4*)&Bs[kk][64 + tx * 4];
            float ra[8] = {am0.x, am0.y, am0.z, am0.w, am1.x, am1.y, am1.z, am1.w};
            float rb[8] = {bn0.x, bn0.y, bn0.z, bn0.w, bn1.x, bn1.y, bn1.z, bn1.w};
#pragma unroll
            for (int i = 0; i < 8; ++i)
#pragma unroll
                for (int j = 0; j < 8; ++j)
                    acc[i][j] = fmaf(ra[i], rb[j], acc[i][j]);
        }
        __syncthreads();
    }

    float* out = g_part + (size_t)z * (NROI * FCOUT);
#pragma unroll
    for (int i = 0; i < 8; ++i) {
        int m = m0 + ((i < 4) ? (ty * 4 + i) : (64 + ty * 4 + (i - 4)));
#pragma unroll
        for (int j = 0; j < 8; ++j) {
            int n = n0 + ((j < 4) ? (tx * 4 + j) : (64 + tx * 4 + (j - 4)));
            out[(size_t)m * FCOUT + n] = acc[i][j];
        }
    }
}

// ---------------------------------------------------------------------------
// Kernel 3: reduce the 49 K-split partials + bias + ReLU -> g_r[256,1024]
// ---------------------------------------------------------------------------
__global__ void reduce_bias_relu(const float* __restrict__ fc_b)
{
    int idx = blockIdx.x * blockDim.x + threadIdx.x;   // 0..262143
    float s = __ldg(fc_b + (idx & (FCOUT - 1)));
#pragma unroll
    for (int zz = 0; zz < NSPLIT; ++zz)
        s += g_part[(size_t)zz * (NROI * FCOUT) + idx];
    g_r[idx] = fmaxf(s, 0.f);
}

// ---------------------------------------------------------------------------
// Kernel 4: cls/reg heads. One block (256 thr) per ROI.
//   cls[21] = r . cls_w_c + cls_b_c    (one warp per class, round-robin)
//   best = argmax (first max wins, matching jnp.argmax)
//   reg[4] = r . reg_w[best*4+q] + reg_b[best*4+q]
// Output layout: [cls_out flattened 256*21][reg_out flattened 256*4]
// ---------------------------------------------------------------------------
__global__ void heads_kernel(const float* __restrict__ cls_w,
                             const float* __restrict__ cls_b,
                             const float* __restrict__ reg_w,
                             const float* __restrict__ reg_b,
                             float* __restrict__ out)
{
    const int roi = blockIdx.x;
    __shared__ float sr[FCOUT];
    __shared__ float scls[NCLS];
    __shared__ int   sbest;

    const int tid  = threadIdx.x;
    const int warp = tid >> 5;
    const int lane = tid & 31;

    for (int i = tid; i < FCOUT; i += 256)
        sr[i] = g_r[(size_t)roi * FCOUT + i];
    __syncthreads();

    for (int cl = warp; cl < NCLS; cl += 8) {
        const float* w = cls_w + (size_t)cl * FCOUT;
        float s = 0.f;
        for (int k = lane; k < FCOUT; k += 32)
            s = fmaf(sr[k], __ldg(w + k), s);
#pragma unroll
        for (int o = 16; o > 0; o >>= 1) s += __shfl_xor_sync(0xFFFFFFFFu, s, o);
        if (lane == 0) {
            s += __ldg(cls_b + cl);
            scls[cl] = s;
            out[(size_t)roi * NCLS + cl] = s;
        }
    }
    __syncthreads();

    if (tid == 0) {
        float best = scls[0];
        int bi = 0;
        for (int c2 = 1; c2 < NCLS; ++c2)
            if (scls[c2] > best) { best = scls[c2]; bi = c2; }
        sbest = bi;
    }
    __syncthreads();

    const int best = sbest;
    if (warp < 4) {
        const float* w = reg_w + (size_t)(best * 4 + warp) * FCOUT;
        float s = 0.f;
        for (int k = lane; k < FCOUT; k += 32)
            s = fmaf(sr[k], __ldg(w + k), s);
#pragma unroll
        for (int o = 16; o > 0; o >>= 1) s += __shfl_xor_sync(0xFFFFFFFFu, s, o);
        if (lane == 0)
            out[NROI * NCLS + roi * 4 + warp] = s + __ldg(reg_b + best * 4 + warp);
    }
}

// ---------------------------------------------------------------------------
// Launch. Inputs (metadata order):
//   0 feature_map f32 [1024,100,50]
//   1 proposals   i32 [256,4]
//   2 fc_w        f32 [1024,50176]
//   3 fc_b        f32 [1024]
//   4 cls_w       f32 [21,1024]
//   5 cls_b       f32 [21]
//   6 reg_w       f32 [84,1024]
//   7 reg_b       f32 [84]
// Output f32: cls_out [256,21] then reg_out [256,4]  (6400 elements)
// ---------------------------------------------------------------------------
extern "C" void kernel_launch(void* const* d_in, const int* in_sizes, int n_in,
                              void* d_out, int out_size)
{
    const float* fmap  = (const float*)d_in[0];
    const int*   props = (const int*)  d_in[1];
    const float* fc_w  = (const float*)d_in[2];
    const float* fc_b  = (const float*)d_in[3];
    const float* cls_w = (const float*)d_in[4];
    const float* cls_b = (const float*)d_in[5];
    const float* reg_w = (const float*)d_in[6];
    const float* reg_b = (const float*)d_in[7];
    float* out = (float*)d_out;

    // 1) ROI pool: 50176 outputs per ROI
    dim3 pg((KDIM + 255) / 256, NROI);
    pool_kernel<<<pg, 256>>>(fmap, props);

    // 2) split-K GEMM: 8 x 2 tiles x 49 K-splits = 784 blocks
    dim3 gg(FCOUT / BN, NROI / BM, NSPLIT);
    gemm_kernel<<<gg, 256>>>(fc_w);

    // 3) reduce + bias + relu
    reduce_bias_relu<<<(NROI * FCOUT) / 256, 256>>>(fc_b);

    // 4) heads
    heads_kernel<<<NROI, 256>>>(cls_w, cls_b, reg_w, reg_b, out);
}

// round 2
// speedup vs baseline: 1.7609x; 1.7609x over previous
#include <cuda_runtime.h>
#include <cuda_bf16.h>
#include <cstdint>

// Problem constants
#define C_CH   1024
#define H_     100
#define W_     50
#define NROI   256
#define NCLS   21
#define KDIM   50176            // 1024 * 49
#define FCOUT  1024
#define ZSPLIT 16
#define KCHUNK (KDIM / ZSPLIT)  // 3136
#define BK     32
#define NIT    (KCHUNK / BK)    // 98
#define BM     128
#define BN     128
#define LDT    40               // padded smem row length (bf16 elems): 32 + 8

// Scratch (__device__ globals: the sanctioned no-cudaMalloc path)
__device__ __align__(256) __nv_bfloat16 g_ah[NROI * KDIM];    // pooled hi
__device__ __align__(256) __nv_bfloat16 g_al[NROI * KDIM];    // pooled lo
__device__ __align__(256) __nv_bfloat16 g_bh[FCOUT * KDIM];   // fc_w hi
__device__ __align__(256) __nv_bfloat16 g_bl[FCOUT * KDIM];   // fc_w lo
__device__ float g_part[ZSPLIT * NROI * FCOUT];               // split-K partials
__device__ float g_r[NROI * FCOUT];                           // relu(fc) activations

// ---------------------------------------------------------------------------
// Kernel 1: ROI adaptive max-pool 7x7 -> hi/lo bf16 split written directly.
// One thread per (roi, c, i, j) output element.
// ---------------------------------------------------------------------------
__global__ void pool_kernel(const float* __restrict__ fmap,
                            const int*   __restrict__ props)
{
    int roi = blockIdx.y;
    int idx = blockIdx.x * blockDim.x + threadIdx.x;   // 0..50175
    if (idx >= KDIM) return;

    int x1 = props[roi * 4 + 0];
    int y1 = props[roi * 4 + 1];
    int x2 = props[roi * 4 + 2];
    int y2 = props[roi * 4 + 3];
    int h0 = max(x1, 0) >> 4;
    int w0 = max(y1, 0) >> 4;
    int h1 = max(x2, 0) >> 4;
    int w1 = max(y2, 0) >> 4;
    int sh = h1 - h0 + 1;
    int sw = w1 - w0 + 1;

    int c = idx / 49;
    int p = idx - c * 49;
    int i = p / 7;
    int j = p - i * 7;

    int hs = h0 + (i * sh) / 7;
    int he = h0 + ((i + 1) * sh + 6) / 7;   // ceil
    int ws = w0 + (j * sw) / 7;
    int we = w0 + ((j + 1) * sw + 6) / 7;   // ceil

    const float* base = fmap + (size_t)c * (H_ * W_);
    float m = -3.402823466e38f;
    for (int hh = hs; hh < he; ++hh) {
        const float* rowp = base + hh * W_;
        for (int ww = ws; ww < we; ++ww)
            m = fmaxf(m, __ldg(rowp + ww));
    }
    size_t off = (size_t)roi * KDIM + idx;
    __nv_bfloat16 h = __float2bfloat16(m);
    __nv_bfloat16 l = __float2bfloat16(m - __bfloat162float(h));
    g_ah[off] = h;
    g_al[off] = l;
}

// ---------------------------------------------------------------------------
// Kernel 1b: fc_w fp32 -> hi/lo bf16 split. One thread per float4.
// ---------------------------------------------------------------------------
__global__ void convert_w(const float4* __restrict__ w)
{
    size_t i = (size_t)blockIdx.x * blockDim.x + threadIdx.x;  // < FCOUT*KDIM/4
    float4 v = w[i];
    __nv_bfloat16 h0 = __float2bfloat16(v.x);
    __nv_bfloat16 h1 = __float2bfloat16(v.y);
    __nv_bfloat16 h2 = __float2bfloat16(v.z);
    __nv_bfloat16 h3 = __float2bfloat16(v.w);
    __nv_bfloat16 l0 = __float2bfloat16(v.x - __bfloat162float(h0));
    __nv_bfloat16 l1 = __float2bfloat16(v.y - __bfloat162float(h1));
    __nv_bfloat16 l2 = __float2bfloat16(v.z - __bfloat162float(h2));
    __nv_bfloat16 l3 = __float2bfloat16(v.w - __bfloat162float(h3));
    __nv_bfloat162* bh = (__nv_bfloat162*)g_bh;
    __nv_bfloat162* bl = (__nv_bfloat162*)g_bl;
    bh[i * 2 + 0] = __nv_bfloat162(h0, h1);
    bh[i * 2 + 1] = __nv_bfloat162(h2, h3);
    bl[i * 2 + 0] = __nv_bfloat162(l0, l1);
    bl[i * 2 + 1] = __nv_bfloat162(l2, l3);
}

// ---------------------------------------------------------------------------
// Kernel 2: bf16x3 tensor-core GEMM, split-K.
// C[m][n] = sum_k A[m][k]*B[n][k] with A = ah+al, B = bh+bl,
// computing ah*bh + ah*bl + al*bh (lo*lo dropped, ~1e-6 rel).
// Block: 128x128 tile, 512 threads = 16 warps (4x4), warp tile 32x32.
// BK=32, double-buffered cp.async. Partial sums per z-slice (deterministic).
// ---------------------------------------------------------------------------
#define TILE_B  (128 * LDT * 2)   // bytes per bf16 tile = 10240
#define STAGE_B (4 * TILE_B)      // Ah, Al, Bh, Bl = 40960
#define SMEM_TOT (2 * STAGE_B)    // 81920

__device__ __forceinline__ void mma16816(float* c, const uint32_t* a, const uint32_t* b)
{
    asm volatile(
        "mma.sync.aligned.m16n8k16.row.col.f32.bf16.bf16.f32 "
        "{%0,%1,%2,%3}, {%4,%5,%6,%7}, {%8,%9}, {%0,%1,%2,%3};\n"
        : "+f"(c[0]), "+f"(c[1]), "+f"(c[2]), "+f"(c[3])
        : "r"(a[0]), "r"(a[1]), "r"(a[2]), "r"(a[3]), "r"(b[0]), "r"(b[1]));
}

__global__ void __launch_bounds__(512, 1)
gemm_bf16x3()
{
    extern __shared__ char smem[];

    const int tid  = threadIdx.x;
    const int warp = tid >> 5;
    const int lane = tid & 31;
    const int n0 = blockIdx.x * BN;
    const int m0 = blockIdx.y * BM;
    const int z  = blockIdx.z;
    const int k0 = z * KCHUNK;

    // warp tile origin within block tile
    const int wm0 = (warp >> 2) * 32;
    const int wn0 = (warp & 3) * 32;

    // global->shared load mapping: 4 threads per 128-row, 16B chunks
    const int lrow = tid >> 2;      // 0..127
    const int lcc  = tid & 3;       // chunk within row (16B each, 64B/row)
    const __nv_bfloat16* gsrc0 = g_ah + (size_t)(m0 + lrow) * KDIM;
    const __nv_bfloat16* gsrc1 = g_al + (size_t)(m0 + lrow) * KDIM;
    const __nv_bfloat16* gsrc2 = g_bh + (size_t)(n0 + lrow) * KDIM;
    const __nv_bfloat16* gsrc3 = g_bl + (size_t)(n0 + lrow) * KDIM;
    const uint32_t sdst_row = (uint32_t)__cvta_generic_to_shared(smem) +
                              (uint32_t)(lrow * (LDT * 2) + lcc * 16);

    float acc[2][4][4];
#pragma unroll
    for (int mt = 0; mt < 2; ++mt)
#pragma unroll
        for (int nt = 0; nt < 4; ++nt)
#pragma unroll
            for (int q = 0; q < 4; ++q) acc[mt][nt][q] = 0.f;

    // ---- async load helper (macro to keep literals in cp.async) ----
#define LOAD_STAGE(stage, kt)                                                   \
    do {                                                                        \
        int kk = k0 + (kt) * BK + lcc * 8;                                      \
        uint32_t d = sdst_row + (stage) * STAGE_B;                              \
        asm volatile("cp.async.cg.shared.global [%0], [%1], 16;" ::             \
                     "r"(d + 0 * TILE_B), "l"(gsrc0 + kk));                     \
        asm volatile("cp.async.cg.shared.global [%0], [%1], 16;" ::             \
                     "r"(d + 1 * TILE_B), "l"(gsrc1 + kk));                     \
        asm volatile("cp.async.cg.shared.global [%0], [%1], 16;" ::             \
                     "r"(d + 2 * TILE_B), "l"(gsrc2 + kk));                     \
        asm volatile("cp.async.cg.shared.global [%0], [%1], 16;" ::             \
                     "r"(d + 3 * TILE_B), "l"(gsrc3 + kk));                     \
        asm volatile("cp.async.commit_group;");                                 \
    } while (0)

    LOAD_STAGE(0, 0);

    for (int it = 0; it < NIT; ++it) {
        if (it + 1 < NIT) {
            LOAD_STAGE((it + 1) & 1, it + 1);
            asm volatile("cp.async.wait_group 1;");
        } else {
            asm volatile("cp.async.wait_group 0;");
        }
        __syncthreads();

        const __nv_bfloat16* Ah = (const __nv_bfloat16*)(smem + (it & 1) * STAGE_B + 0 * TILE_B);
        const __nv_bfloat16* Al = (const __nv_bfloat16*)(smem + (it & 1) * STAGE_B + 1 * TILE_B);
        const __nv_bfloat16* Bh = (const __nv_bfloat16*)(smem + (it & 1) * STAGE_B + 2 * TILE_B);
        const __nv_bfloat16* Bl = (const __nv_bfloat16*)(smem + (it & 1) * STAGE_B + 3 * TILE_B);

#pragma unroll
        for (int ks = 0; ks < 2; ++ks) {
            const int kb = ks * 16 + (lane & 3) * 2;   // k col of this thread
            const int ar = lane >> 2;                  // row-in-tile 0..7

            uint32_t fah[2][4], fal[2][4], fbh[4][2], fbl[4][2];
#pragma unroll
            for (int mt = 0; mt < 2; ++mt) {
                int r = wm0 + mt * 16 + ar;
                fah[mt][0] = *(const uint32_t*)&Ah[r * LDT + kb];
                fah[mt][1] = *(const uint32_t*)&Ah[(r + 8) * LDT + kb];
                fah[mt][2] = *(const uint32_t*)&Ah[r * LDT + kb + 8];
                fah[mt][3] = *(const uint32_t*)&Ah[(r + 8) * LDT + kb + 8];
                fal[mt][0] = *(const uint32_t*)&Al[r * LDT + kb];
                fal[mt][1] = *(const uint32_t*)&Al[(r + 8) * LDT + kb];
                fal[mt][2] = *(const uint32_t*)&Al[r * LDT + kb + 8];
                fal[mt][3] = *(const uint32_t*)&Al[(r + 8) * LDT + kb + 8];
            }
#pragma unroll
            for (int nt = 0; nt < 4; ++nt) {
                int rn = wn0 + nt * 8 + ar;
                fbh[nt][0] = *(const uint32_t*)&Bh[rn * LDT + kb];
                fbh[nt][1] = *(const uint32_t*)&Bh[rn * LDT + kb + 8];
                fbl[nt][0] = *(const uint32_t*)&Bl[rn * LDT + kb];
                fbl[nt][1] = *(const uint32_t*)&Bl[rn * LDT + kb + 8];
            }
#pragma unroll
            for (int mt = 0; mt < 2; ++mt)
#pragma unroll
                for (int nt = 0; nt < 4; ++nt) {
                    mma16816(acc[mt][nt], fah[mt], fbh[nt]);
                    mma16816(acc[mt][nt], fah[mt], fbl[nt]);
                    mma16816(acc[mt][nt], fal[mt], fbh[nt]);
                }
        }
        __syncthreads();
    }

    float* outp = g_part + (size_t)z * (NROI * FCOUT);
#pragma unroll
    for (int mt = 0; mt < 2; ++mt)
#pragma unroll
        for (int nt = 0; nt < 4; ++nt) {
            int m = m0 + wm0 + mt * 16 + (lane >> 2);
            int n = n0 + wn0 + nt * 8 + (lane & 3) * 2;
            float2 v0 = make_float2(acc[mt][nt][0], acc[mt][nt][1]);
            float2 v1 = make_float2(acc[mt][nt][2], acc[mt][nt][3]);
            *(float2*)&outp[(size_t)m * FCOUT + n] = v0;
            *(float2*)&outp[(size_t)(m + 8) * FCOUT + n] = v1;
        }
}

// ---------------------------------------------------------------------------
// Kernel 3: reduce ZSPLIT partials + bias + ReLU -> g_r[256,1024]
// ---------------------------------------------------------------------------
__global__ void reduce_bias_relu(const float* __restrict__ fc_b)
{
    int idx = blockIdx.x * blockDim.x + threadIdx.x;
    float s = __ldg(fc_b + (idx & (FCOUT - 1)));
#pragma unroll
    for (int zz = 0; zz < ZSPLIT; ++zz)
        s += g_part[(size_t)zz * (NROI * FCOUT) + idx];
    g_r[idx] = fmaxf(s, 0.f);
}

// ---------------------------------------------------------------------------
// Kernel 4: cls/reg heads (unchanged, 13.5us, fine for now)
// ---------------------------------------------------------------------------
__global__ void heads_kernel(const float* __restrict__ cls_w,
                             const float* __restrict__ cls_b,
                             const float* __restrict__ reg_w,
                             const float* __restrict__ reg_b,
                             float* __restrict__ out)
{
    const int roi = blockIdx.x;
    __shared__ float sr[FCOUT];
    __shared__ float scls[NCLS];
    __shared__ int   sbest;

    const int tid  = threadIdx.x;
    const int warp = tid >> 5;
    const int lane = tid & 31;

    for (int i = tid; i < FCOUT; i += 256)
        sr[i] = g_r[(size_t)roi * FCOUT + i];
    __syncthreads();

    for (int cl = warp; cl < NCLS; cl += 8) {
        const float* w = cls_w + (size_t)cl * FCOUT;
        float s = 0.f;
        for (int k = lane; k < FCOUT; k += 32)
            s = fmaf(sr[k], __ldg(w + k), s);
#pragma unroll
        for (int o = 16; o > 0; o >>= 1) s += __shfl_xor_sync(0xFFFFFFFFu, s, o);
        if (lane == 0) {
            s += __ldg(cls_b + cl);
            scls[cl] = s;
            out[(size_t)roi * NCLS + cl] = s;
        }
    }
    __syncthreads();

    if (tid == 0) {
        float best = scls[0];
        int bi = 0;
        for (int c2 = 1; c2 < NCLS; ++c2)
            if (scls[c2] > best) { best = scls[c2]; bi = c2; }
        sbest = bi;
    }
    __syncthreads();

    const int best = sbest;
    if (warp < 4) {
        const float* w = reg_w + (size_t)(best * 4 + warp) * FCOUT;
        float s = 0.f;
        for (int k = lane; k < FCOUT; k += 32)
            s = fmaf(sr[k], __ldg(w + k), s);
#pragma unroll
        for (int o = 16; o > 0; o >>= 1) s += __shfl_xor_sync(0xFFFFFFFFu, s, o);
        if (lane == 0)
            out[NROI * NCLS + roi * 4 + warp] = s + __ldg(reg_b + best * 4 + warp);
    }
}

// ---------------------------------------------------------------------------
// Launch. Inputs (metadata order):
//   0 feature_map f32 [1024,100,50], 1 proposals i32 [256,4],
//   2 fc_w f32 [1024,50176], 3 fc_b f32 [1024],
//   4 cls_w f32 [21,1024], 5 cls_b f32 [21],
//   6 reg_w f32 [84,1024], 7 reg_b f32 [84]
// Output f32: cls_out [256,21] ++ reg_out [256,4]
// ---------------------------------------------------------------------------
extern "C" void kernel_launch(void* const* d_in, const int* in_sizes, int n_in,
                              void* d_out, int out_size)
{
    const float* fmap  = (const float*)d_in[0];
    const int*   props = (const int*)  d_in[1];
    const float* fc_w  = (const float*)d_in[2];
    const float* fc_b  = (const float*)d_in[3];
    const float* cls_w = (const float*)d_in[4];
    const float* cls_b = (const float*)d_in[5];
    const float* reg_w = (const float*)d_in[6];
    const float* reg_b = (const float*)d_in[7];
    float* out = (float*)d_out;

    cudaFuncSetAttribute(gemm_bf16x3,
                         cudaFuncAttributeMaxDynamicSharedMemorySize, SMEM_TOT);

    // 1) fc_w split (independent of pool)
    convert_w<<<(FCOUT * KDIM / 4) / 256, 256>>>((const float4*)fc_w);

    // 2) ROI pool -> hi/lo bf16
    dim3 pg((KDIM + 255) / 256, NROI);
    pool_kernel<<<pg, 256>>>(fmap, props);

    // 3) bf16x3 GEMM: 8 x 2 tiles x 16 K-splits
    dim3 gg(FCOUT / BN, NROI / BM, ZSPLIT);
    gemm_bf16x3<<<gg, 512, SMEM_TOT>>>();

    // 4) reduce + bias + relu
    reduce_bias_relu<<<(NROI * FCOUT) / 256, 256>>>(fc_b);

    // 5) heads
    heads_kernel<<<NROI, 256>>>(cls_w, cls_b, reg_w, reg_b, out);
}

// round 6
// speedup vs baseline: 2.1708x; 1.2328x over previous
#include <cuda_runtime.h>
#include <cuda_bf16.h>
#include <cstdint>

// Problem constants
#define C_CH   1024
#define H_     100
#define W_     50
#define NROI   256
#define NCLS   21
#define KDIM   50176            // 1024 * 49
#define FCOUT  1024
#define ZSPLIT 16
#define KCHUNK (KDIM / ZSPLIT)  // 3136
#define BKK    32               // K per smem stage
#define NIT    (KCHUNK / BKK)   // 98
#define BM     128
#define BN     128

// smem stage layout: 4 tiles of 128 rows x 32 bf16 (64B rows, XOR swizzled)
#define TS_AH   0
#define TS_AL   8192
#define TS_BH   16384
#define TS_BL   24576
#define STAGE_B 32768
#define SMEM_DYN (2 * STAGE_B)

// Scratch (__device__ globals: no cudaMalloc allowed)
__device__ __align__(256) __nv_bfloat16 g_ah[NROI * KDIM];
__device__ __align__(256) __nv_bfloat16 g_al[NROI * KDIM];
__device__ __align__(256) __nv_bfloat16 g_bh[FCOUT * KDIM];
__device__ __align__(256) __nv_bfloat16 g_bl[FCOUT * KDIM];
__device__ float g_part[ZSPLIT * NROI * FCOUT];
__device__ float g_r[NROI * FCOUT];

// ---------------------------------------------------------------------------
// Kernel 1: ROI adaptive max-pool 7x7 -> hi/lo bf16 split
// ---------------------------------------------------------------------------
__global__ void pool_kernel(const float* __restrict__ fmap,
                            const int*   __restrict__ props)
{
    int roi = blockIdx.y;
    int idx = blockIdx.x * blockDim.x + threadIdx.x;
    if (idx >= KDIM) return;

    int x1 = props[roi * 4 + 0];
    int y1 = props[roi * 4 + 1];
    int x2 = props[roi * 4 + 2];
    int y2 = props[roi * 4 + 3];
    int h0 = max(x1, 0) >> 4;
    int w0 = max(y1, 0) >> 4;
    int h1 = max(x2, 0) >> 4;
    int w1 = max(y2, 0) >> 4;
    int sh = h1 - h0 + 1;
    int sw = w1 - w0 + 1;

    int c = idx / 49;
    int p = idx - c * 49;
    int i = p / 7;
    int j = p - i * 7;

    int hs = h0 + (i * sh) / 7;
    int he = h0 + ((i + 1) * sh + 6) / 7;
    int ws = w0 + (j * sw) / 7;
    int we = w0 + ((j + 1) * sw + 6) / 7;

    const float* base = fmap + (size_t)c * (H_ * W_);
    float m = -3.402823466e38f;
    for (int hh = hs; hh < he; ++hh) {
        const float* rowp = base + hh * W_;
        for (int ww = ws; ww < we; ++ww)
            m = fmaxf(m, __ldg(rowp + ww));
    }
    size_t off = (size_t)roi * KDIM + idx;
    __nv_bfloat16 h = __float2bfloat16(m);
    __nv_bfloat16 l = __float2bfloat16(m - __bfloat162float(h));
    g_ah[off] = h;
    g_al[off] = l;
}

// ---------------------------------------------------------------------------
// Kernel 1b: fc_w fp32 -> hi/lo bf16 split
// ---------------------------------------------------------------------------
__global__ void convert_w(const float4* __restrict__ w)
{
    size_t i = (size_t)blockIdx.x * blockDim.x + threadIdx.x;
    float4 v = w[i];
    __nv_bfloat16 h0 = __float2bfloat16(v.x);
    __nv_bfloat16 h1 = __float2bfloat16(v.y);
    __nv_bfloat16 h2 = __float2bfloat16(v.z);
    __nv_bfloat16 h3 = __float2bfloat16(v.w);
    __nv_bfloat16 l0 = __float2bfloat16(v.x - __bfloat162float(h0));
    __nv_bfloat16 l1 = __float2bfloat16(v.y - __bfloat162float(h1));
    __nv_bfloat16 l2 = __float2bfloat16(v.z - __bfloat162float(h2));
    __nv_bfloat16 l3 = __float2bfloat16(v.w - __bfloat162float(h3));
    __nv_bfloat162* bh = (__nv_bfloat162*)g_bh;
    __nv_bfloat162* bl = (__nv_bfloat162*)g_bl;
    bh[i * 2 + 0] = __nv_bfloat162(h0, h1);
    bh[i * 2 + 1] = __nv_bfloat162(h2, h3);
    bl[i * 2 + 0] = __nv_bfloat162(l0, l1);
    bl[i * 2 + 1] = __nv_bfloat162(l2, l3);
}

// ---------------------------------------------------------------------------
// Kernel 2: bf16x3 mma.sync GEMM v2 — ldmatrix, XOR-swizzled smem,
// fragment reuse across the 3 precision terms, split-K Z=16.
// 128x128 block, 8 warps (2m x 4n), warp tile 64x32, BK=32, double buffer.
// ---------------------------------------------------------------------------
__device__ __forceinline__ void mma16816(float* c, const uint32_t* a, const uint32_t* b)
{
    asm volatile(
        "mma.sync.aligned.m16n8k16.row.col.f32.bf16.bf16.f32 "
        "{%0,%1,%2,%3}, {%4,%5,%6,%7}, {%8,%9}, {%0,%1,%2,%3};\n"
        : "+f"(c[0]), "+f"(c[1]), "+f"(c[2]), "+f"(c[3])
        : "r"(a[0]), "r"(a[1]), "r"(a[2]), "r"(a[3]), "r"(b[0]), "r"(b[1]));
}

__device__ __forceinline__ void ldm4(uint32_t* r, uint32_t addr)
{
    asm volatile("ldmatrix.sync.aligned.m8n8.x4.shared.b16 {%0,%1,%2,%3}, [%4];"
                 : "=r"(r[0]), "=r"(r[1]), "=r"(r[2]), "=r"(r[3]) : "r"(addr));
}

__global__ void __launch_bounds__(256, 2)
gemm_mma()
{
    extern __shared__ char dynsm[];
    const uint32_t dynb = (uint32_t)__cvta_generic_to_shared(dynsm);

    const int tid  = threadIdx.x;
    const int warp = tid >> 5;
    const int lane = tid & 31;
    const int n0 = blockIdx.x * BN;
    const int m0 = blockIdx.y * BM;
    const int z  = blockIdx.z;
    const int k0 = z * KCHUNK;

    // ---- global->shared mapping ----
    // step s (0..7): tile = s>>1 (Ah,Al,Bh,Bl), row = (tid>>2) + 64*(s&1),
    // chunk = tid&3 (16B). Swizzle: chunk ^ ((row>>1)&3), s-invariant.
    const int rbase = tid >> 2;          // 0..63
    const int chunk = tid & 3;
    const uint32_t swz16 = (uint32_t)((chunk ^ ((rbase >> 1) & 3)) << 4);

    const __nv_bfloat16* tb[4] = {
        g_ah + (size_t)m0 * KDIM + k0 + chunk * 8,
        g_al + (size_t)m0 * KDIM + k0 + chunk * 8,
        g_bh + (size_t)n0 * KDIM + k0 + chunk * 8,
        g_bl + (size_t)n0 * KDIM + k0 + chunk * 8
    };
    const uint32_t toff[4] = {TS_AH, TS_AL, TS_BH, TS_BL};

#define LOAD_STAGE(stg, koff)                                                   \
    do {                                                                        \
        _Pragma("unroll")                                                       \
        for (int _s = 0; _s < 8; ++_s) {                                        \
            int _row = rbase + 64 * (_s & 1);                                   \
            uint32_t _d = dynb + (stg) * STAGE_B + toff[_s >> 1] +              \
                          (uint32_t)(_row * 64) + swz16;                        \
            const __nv_bfloat16* _g = tb[_s >> 1] + (size_t)_row * KDIM + (koff);\
            asm volatile("cp.async.cg.shared.global [%0], [%1], 16;"            \
                         :: "r"(_d), "l"(_g) : "memory");                       \
        }                                                                       \
        asm volatile("cp.async.commit_group;" ::: "memory");                    \
    } while (0)

    // ---- per-warp fragment addressing ----
    const int wm = (warp & 1) * 64;
    const int wn = (warp >> 1) * 32;

    uint32_t aOff[4], aXr[4], bOff[2], bXr[2];
#pragma unroll
    for (int f = 0; f < 4; ++f) {
        int r = wm + f * 16 + (lane & 15);
        aOff[f] = (uint32_t)(r * 64);
        aXr[f]  = (uint32_t)((r >> 1) & 3);
    }
#pragma unroll
    for (int g = 0; g < 2; ++g) {
        int n = wn + g * 16 + (lane & 7) + ((lane >> 4) << 3);
        bOff[g] = (uint32_t)(n * 64);
        bXr[g]  = (uint32_t)((n >> 1) & 3);
    }
    const uint32_t aCk = (uint32_t)(lane >> 4);        // 0/1: k8 half for A
    const uint32_t bCk = (uint32_t)((lane >> 3) & 1);  // 0/1: k8 half for B

    float acc[4][4][4];
#pragma unroll
    for (int f = 0; f < 4; ++f)
#pragma unroll
        for (int nf = 0; nf < 4; ++nf)
#pragma unroll
            for (int q = 0; q < 4; ++q) acc[f][nf][q] = 0.f;

    LOAD_STAGE(0, 0);
    LOAD_STAGE(1, BKK);

    for (int it = 0; it < NIT; ++it) {
        const int s = it & 1;
        if (it + 1 < NIT)
            asm volatile("cp.async.wait_group 1;" ::: "memory");
        else
            asm volatile("cp.async.wait_group 0;" ::: "memory");
        __syncthreads();

        const uint32_t sb = dynb + s * STAGE_B;
#pragma unroll
        for (int ks = 0; ks < 2; ++ks) {
            const uint32_t ck = (uint32_t)(ks * 2);

            uint32_t ah[4][4];
#pragma unroll
            for (int f = 0; f < 4; ++f)
                ldm4(ah[f], sb + TS_AH + aOff[f] + (((ck + aCk) ^ aXr[f]) << 4));
            uint32_t bh[2][4];
#pragma unroll
            for (int g = 0; g < 2; ++g)
                ldm4(bh[g], sb + TS_BH + bOff[g] + (((ck + bCk) ^ bXr[g]) << 4));
#pragma unroll
            for (int f = 0; f < 4; ++f)
#pragma unroll
                for (int g = 0; g < 2; ++g) {
                    mma16816(acc[f][g * 2 + 0], ah[f], &bh[g][0]);
                    mma16816(acc[f][g * 2 + 1], ah[f], &bh[g][2]);
                }

            uint32_t bl[2][4];
#pragma unroll
            for (int g = 0; g < 2; ++g)
                ldm4(bl[g], sb + TS_BL + bOff[g] + (((ck + bCk) ^ bXr[g]) << 4));
#pragma unroll
            for (int f = 0; f < 4; ++f)
#pragma unroll
                for (int g = 0; g < 2; ++g) {
                    mma16816(acc[f][g * 2 + 0], ah[f], &bl[g][0]);
                    mma16816(acc[f][g * 2 + 1], ah[f], &bl[g][2]);
                }

            uint32_t al[4][4];
#pragma unroll
            for (int f = 0; f < 4; ++f)
                ldm4(al[f], sb + TS_AL + aOff[f] + (((ck + aCk) ^ aXr[f]) << 4));
#pragma unroll
            for (int f = 0; f < 4; ++f)
#pragma unroll
                for (int g = 0; g < 2; ++g) {
                    mma16816(acc[f][g * 2 + 0], al[f], &bh[g][0]);
                    mma16816(acc[f][g * 2 + 1], al[f], &bh[g][2]);
                }
        }
        __syncthreads();

        if (it + 2 < NIT)
            LOAD_STAGE(s, (it + 2) * BKK);
    }

    // ---- epilogue: acc -> g_part[z] ----
    float* op = g_part + (size_t)z * (NROI * FCOUT);
#pragma unroll
    for (int f = 0; f < 4; ++f) {
        int r = m0 + wm + f * 16 + (lane >> 2);
#pragma unroll
        for (int nf = 0; nf < 4; ++nf) {
            int c = n0 + wn + nf * 8 + (lane & 3) * 2;
            *(float2*)&op[(size_t)r * FCOUT + c] =
                make_float2(acc[f][nf][0], acc[f][nf][1]);
            *(float2*)&op[(size_t)(r + 8) * FCOUT + c] =
                make_float2(acc[f][nf][2], acc[f][nf][3]);
        }
    }
#undef LOAD_STAGE
}

// ---------------------------------------------------------------------------
// Kernel 3: reduce ZSPLIT partials + bias + ReLU
// ---------------------------------------------------------------------------
__global__ void reduce_bias_relu(const float* __restrict__ fc_b)
{
    int idx = blockIdx.x * blockDim.x + threadIdx.x;
    float s = __ldg(fc_b + (idx & (FCOUT - 1)));
#pragma unroll
    for (int zz = 0; zz < ZSPLIT; ++zz)
        s += g_part[(size_t)zz * (NROI * FCOUT) + idx];
    g_r[idx] = fmaxf(s, 0.f);
}

// ---------------------------------------------------------------------------
// Kernel 4: cls/reg heads
// ---------------------------------------------------------------------------
__global__ void heads_kernel(const float* __restrict__ cls_w,
                             const float* __restrict__ cls_b,
                             const float* __restrict__ reg_w,
                             const float* __restrict__ reg_b,
                             float* __restrict__ out)
{
    const int roi = blockIdx.x;
    __shared__ float sr[FCOUT];
    __shared__ float scls[NCLS];
    __shared__ int   sbest;

    const int tid  = threadIdx.x;
    const int warp = tid >> 5;
    const int lane = tid & 31;

    for (int i = tid; i < FCOUT; i += 256)
        sr[i] = g_r[(size_t)roi * FCOUT + i];
    __syncthreads();

    for (int cl = warp; cl < NCLS; cl += 8) {
        const float* w = cls_w + (size_t)cl * FCOUT;
        float s = 0.f;
        for (int k = lane; k < FCOUT; k += 32)
            s = fmaf(sr[k], __ldg(w + k), s);
#pragma unroll
        for (int o = 16; o > 0; o >>= 1) s += __shfl_xor_sync(0xFFFFFFFFu, s, o);
        if (lane == 0) {
            s += __ldg(cls_b + cl);
            scls[cl] = s;
            out[(size_t)roi * NCLS + cl] = s;
        }
    }
    __syncthreads();

    if (tid == 0) {
        float best = scls[0];
        int bi = 0;
        for (int c2 = 1; c2 < NCLS; ++c2)
            if (scls[c2] > best) { best = scls[c2]; bi = c2; }
        sbest = bi;
    }
    __syncthreads();

    const int best = sbest;
    if (warp < 4) {
        const float* w = reg_w + (size_t)(best * 4 + warp) * FCOUT;
        float s = 0.f;
        for (int k = lane; k < FCOUT; k += 32)
            s = fmaf(sr[k], __ldg(w + k), s);
#pragma unroll
        for (int o = 16; o > 0; o >>= 1) s += __shfl_xor_sync(0xFFFFFFFFu, s, o);
        if (lane == 0)
            out[NROI * NCLS + roi * 4 + warp] = s + __ldg(reg_b + best * 4 + warp);
    }
}

// ---------------------------------------------------------------------------
// Launch
// ---------------------------------------------------------------------------
extern "C" void kernel_launch(void* const* d_in, const int* in_sizes, int n_in,
                              void* d_out, int out_size)
{
    const float* fmap  = (const float*)d_in[0];
    const int*   props = (const int*)  d_in[1];
    const float* fc_w  = (const float*)d_in[2];
    const float* fc_b  = (const float*)d_in[3];
    const float* cls_w = (const float*)d_in[4];
    const float* cls_b = (const float*)d_in[5];
    const float* reg_w = (const float*)d_in[6];
    const float* reg_b = (const float*)d_in[7];
    float* out = (float*)d_out;

    cudaFuncSetAttribute(gemm_mma,
                         cudaFuncAttributeMaxDynamicSharedMemorySize, SMEM_DYN);

    // 1) fc_w split
    convert_w<<<(FCOUT * KDIM / 4) / 256, 256>>>((const float4*)fc_w);

    // 2) ROI pool -> hi/lo bf16
    dim3 pg((KDIM + 255) / 256, NROI);
    pool_kernel<<<pg, 256>>>(fmap, props);

    // 3) mma.sync GEMM v2: 8 N-blocks x 2 M-blocks x 16 K-splits = 256 blocks
    dim3 gg(FCOUT / BN, NROI / BM, ZSPLIT);
    gemm_mma<<<gg, 256, SMEM_DYN>>>();

    // 4) reduce + bias + relu
    reduce_bias_relu<<<(NROI * FCOUT) / 256, 256>>>(fc_b);

    // 5) heads
    heads_kernel<<<NROI, 256>>>(cls_w, cls_b, reg_w, reg_b, out);
}